// round 13
// baseline (speedup 1.0000x reference)
#include <cuda_runtime.h>
#include <cuda_fp16.h>
#include <cstdint>

// Problem constants
#define KW    8
#define BB    16
#define LL    2048
#define DD    128
#define LP    (LL + 7)      // padded rows per batch
#define GD    384           // 3*D gate dim
#define RT    (BB * LP)     // 32880 total xproj rows

#define HS    136           // SMEM row stride in halves (272B, conflict-free ldmatrix)
#define W_BYTES (GD * HS * 2)                  // 104448

// pre kernel: 256-row tiles, 512 threads, grid 128+1 (one wave)
#define PRE_NC   128
#define PRE_SMEM (256 * HS * 2 + W_BYTES)      // 174080
// main kernel: 256-row tiles, 512 threads (16 warps x 16 rows), h in registers
#define MAIN_NC  128
#define MAIN_SMEM (W_BYTES + 512)              // W + b_hh n-slab cache

// fp16 xproj, plane-major lane-contiguous layout:
//   plane sq = s*4+q (12 planes), then [row RT][tig 4][8 halves]
#define PS_H ((size_t)RT * 32)   // plane stride in halves
__device__ __align__(16) __half g_xq[12 * PS_H];

// ---------------- helpers ----------------
static __device__ __forceinline__ uint32_t smem_u32(const void* p) {
    uint32_t a;
    asm("{ .reg .u64 t; cvta.to.shared.u64 t, %1; cvt.u32.u64 %0, t; }" : "=r"(a) : "l"(p));
    return a;
}
// single-MUFU activations (MUFU.TANH)
static __device__ __forceinline__ float tanhf_(float x) {
    float y; asm("tanh.approx.f32 %0,%1;" : "=f"(y) : "f"(x)); return y;
}
static __device__ __forceinline__ float sigf(float x) {
    return fmaf(0.5f, tanhf_(0.5f * x), 0.5f);
}

static __device__ __forceinline__ uint32_t pack_h2(float a, float b) {
    __half2 h = __floats2half2_rn(a, b);
    return *reinterpret_cast<uint32_t*>(&h);
}
static __device__ __forceinline__ float2 unpack_h2(uint32_t u) {
    __half2 h = *reinterpret_cast<__half2*>(&u);
    return make_float2(__low2float(h), __high2float(h));
}

static __device__ __forceinline__ void ldsm4(uint32_t* r, uint32_t addr) {
    asm volatile("ldmatrix.sync.aligned.m8n8.x4.shared.b16 {%0,%1,%2,%3},[%4];"
                 : "=r"(r[0]), "=r"(r[1]), "=r"(r[2]), "=r"(r[3]) : "r"(addr));
}
static __device__ __forceinline__ void mma16816(float* d, const uint32_t* a, const uint32_t* b) {
    asm volatile("mma.sync.aligned.m16n8k16.row.col.f32.f16.f16.f32 "
                 "{%0,%1,%2,%3},{%4,%5,%6,%7},{%8,%9},{%0,%1,%2,%3};"
                 : "+f"(d[0]), "+f"(d[1]), "+f"(d[2]), "+f"(d[3])
                 : "r"(a[0]), "r"(a[1]), "r"(a[2]), "r"(a[3]), "r"(b[0]), "r"(b[1]));
}

// load [384,128] fp32 weight -> fp16 SMEM [384][HS]
template<int NT>
static __device__ __forceinline__ void load_w(__half* wT, const float* __restrict__ W, int tid) {
    #pragma unroll
    for (int j = 0; j < (GD * DD / 4) / NT; ++j) {
        int idx = (tid + j * NT) * 4;
        int g = idx >> 7, k = idx & 127;
        float4 v = *(const float4*)(W + idx);
        __half2* p = (__half2*)&wT[g * HS + k];
        p[0] = __floats2half2_rn(v.x, v.y);
        p[1] = __floats2half2_rn(v.z, v.w);
    }
}

// ===================== Kernel 1: xproj precompute (512 thr, 1 wave) =========
static __device__ __forceinline__ void gemm_slab16(float acc[16][4], uint32_t aAddr, uint32_t bAddr) {
    #pragma unroll
    for (int k = 0; k < 8; ++k) {
        uint32_t a[4];
        ldsm4(a, aAddr + k * 32);
        #pragma unroll
        for (int np = 0; np < 8; ++np) {
            uint32_t bb[4];
            ldsm4(bb, bAddr + np * (16 * HS * 2) + k * 32);
            mma16816(acc[2 * np],     a, bb);
            mma16816(acc[2 * np + 1], a, bb + 2);
        }
    }
}

__global__ void __launch_bounds__(512, 1)
lrnn_pre(const float* __restrict__ x, const float* __restrict__ W_ih,
         const float* __restrict__ b_ih, const float* __restrict__ b_hh) {
    if (blockIdx.x == PRE_NC) {   // pad rows: pure bias, plane-major layout
        for (int i = threadIdx.x; i < BB * 7 * GD; i += 512) {
            int b = i / (7 * GD);
            int rr = i % (7 * GD);
            int p = rr / GD, gcol = rr % GD;
            float v = b_ih[gcol] + (gcol < 256 ? b_hh[gcol] : 0.f);
            int s = gcol >> 7, w128 = gcol & 127;
            int q = w128 >> 5, r32 = w128 & 31;
            int jn = r32 >> 3, tg = (r32 & 7) >> 1, ii = r32 & 1;
            size_t rem = (size_t)tg * 8 + jn * 2 + ii;
            g_xq[(size_t)(s * 4 + q) * PS_H + (size_t)(b * LP + p) * 32 + rem] = __float2half_rn(v);
        }
        return;
    }
    extern __shared__ char smem[];
    __half* xT = (__half*)smem;
    __half* wT = (__half*)(smem + 256 * HS * 2);
    int tid = threadIdx.x, w = tid >> 5, lane = tid & 31;
    int c = blockIdx.x, b = c >> 3, l0 = (c & 7) << 8;

    load_w<512>(wT, W_ih, tid);
    __syncthreads();

    int m0 = w * 16;
    int g = lane >> 2, tig = lane & 3;
    int rA = m0 + g;

    {
        int row = m0 + (lane >> 1);
        int cb = (lane & 1) * 64;
        const float* xr = x + (size_t)(b * LL + l0 + row) * DD + cb;
        __half* dst = &xT[row * HS + cb];
        #pragma unroll
        for (int q = 0; q < 16; ++q) {
            float4 v = *(const float4*)(xr + q * 4);
            __half2* p = (__half2*)(dst + q * 4);
            p[0] = __floats2half2_rn(v.x, v.y);
            p[1] = __floats2half2_rn(v.z, v.w);
        }
    }
    __syncwarp();

    uint32_t aAddr = smem_u32(&xT[(m0 + (lane & 15)) * HS + ((lane >> 4) << 3)]);
    int gOff = (lane & 7) + ((lane >> 4) << 3);
    int colOff = ((lane >> 3) & 1) << 3;
    uint32_t wAddr0 = smem_u32(&wT[gOff * HS + colOff]);

    size_t rowA = (size_t)(b * LP + 7 + l0 + rA);

    #pragma unroll 1
    for (int s = 0; s < 3; ++s) {
        float acc[16][4];
        #pragma unroll
        for (int j = 0; j < 16; ++j) { acc[j][0] = acc[j][1] = acc[j][2] = acc[j][3] = 0.f; }
        gemm_slab16(acc, aAddr, wAddr0 + s * (128 * HS * 2));

        int sc = s * 128;
        #pragma unroll
        for (int q = 0; q < 4; ++q) {
            uint32_t pA[4], pB[4];
            #pragma unroll
            for (int jn = 0; jn < 4; ++jn) {
                int j = q * 4 + jn;
                int cc = j * 8 + 2 * tig;
                float2 bi = *(const float2*)(b_ih + sc + cc);
                float bx = 0.f, by = 0.f;
                if (s < 2) { float2 bh = *(const float2*)(b_hh + sc + cc); bx = bh.x; by = bh.y; }
                pA[jn] = pack_h2(acc[j][0] + bi.x + bx, acc[j][1] + bi.y + by);
                pB[jn] = pack_h2(acc[j][2] + bi.x + bx, acc[j][3] + bi.y + by);
            }
            __half* dst = g_xq + (size_t)(s * 4 + q) * PS_H + rowA * 32 + tig * 8;
            *(uint4*)dst = make_uint4(pA[0], pA[1], pA[2], pA[3]);
            *(uint4*)(dst + 8 * 32) = make_uint4(pB[0], pB[1], pB[2], pB[3]);   // row rA+8
        }
    }
}

// ===================== Kernel 2: 8-step local GRU =====================
// 512 threads = 16 warps x 16 rows, grid 128 = 1 wave. h entirely in registers.
// Per quarter: issue xq LDGs -> rz GEMM (hides LDG latency) -> sigmoids ->
// n GEMM -> tanh + update. No prefetch (loads ARE the prefetch).

static __device__ __forceinline__ void gemm_q2(float ar[4][4], float az[4][4],
                                               const uint32_t aF[8][4], uint32_t bq) {
    #pragma unroll
    for (int k = 0; k < 8; ++k) {
        #pragma unroll
        for (int p = 0; p < 2; ++p) {
            uint32_t br[4], bz[4];
            ldsm4(br, bq + p * (16 * HS * 2) + k * 32);
            ldsm4(bz, bq + 128 * HS * 2 + p * (16 * HS * 2) + k * 32);
            mma16816(ar[2 * p],     aF[k], br);
            mma16816(ar[2 * p + 1], aF[k], br + 2);
            mma16816(az[2 * p],     aF[k], bz);
            mma16816(az[2 * p + 1], aF[k], bz + 2);
        }
    }
}

static __device__ __forceinline__ void gemm_q1n(float an[4][4],
                                                const uint32_t aF[8][4], uint32_t bq) {
    #pragma unroll
    for (int k = 0; k < 8; ++k) {
        #pragma unroll
        for (int p = 0; p < 2; ++p) {
            uint32_t bn[4];
            ldsm4(bn, bq + p * (16 * HS * 2) + k * 32);
            mma16816(an[2 * p],     aF[k], bn);
            mma16816(an[2 * p + 1], aF[k], bn + 2);
        }
    }
}

__global__ void __launch_bounds__(512, 1)
lrnn_main(const float* __restrict__ W_hh, const float* __restrict__ b_hh,
          float* __restrict__ out) {
    extern __shared__ char smem[];
    __half* wT = (__half*)smem;
    float* bhn = (float*)(smem + W_BYTES);
    int tid = threadIdx.x, w = tid >> 5, lane = tid & 31;
    int c = blockIdx.x, b = c >> 3, l0 = (c & 7) << 8;

    load_w<512>(wT, W_hh, tid);
    if (tid < 128) bhn[tid] = b_hh[256 + tid];
    __syncthreads();

    int m0 = w * 16;
    int g = lane >> 2, tig = lane & 3;
    int rA = m0 + g;

    int gOff = (lane & 7) + ((lane >> 4) << 3);
    int colOff = ((lane >> 3) & 1) << 3;
    uint32_t wA = smem_u32(&wT[gOff * HS + colOff]);

    // per-thread xq base (plane-relative): row at window step t -> +t*32 halves
    const __half* xqb = g_xq + (size_t)(b * LP + l0 + m0 + g) * 32 + tig * 8;

    uint32_t aF[8][4], nA[8][4];

    // ---------- t = 0 (h_prev = 0) ----------
    #pragma unroll
    for (int q = 0; q < 4; ++q) {
        const __half* pr = xqb + (size_t)(0 * 4 + q) * PS_H;
        const __half* pz = xqb + (size_t)(1 * 4 + q) * PS_H;
        const __half* pn = xqb + (size_t)(2 * 4 + q) * PS_H;
        uint4 vrA = *(const uint4*)pr,         vrB = *(const uint4*)(pr + 256);
        uint4 vzA = *(const uint4*)pz,         vzB = *(const uint4*)(pz + 256);
        uint4 vnA = *(const uint4*)pn,         vnB = *(const uint4*)(pn + 256);
        #pragma unroll
        for (int jn = 0; jn < 4; ++jn) {
            float2 xrA = unpack_h2(((const uint32_t*)&vrA)[jn]);
            float2 xrB = unpack_h2(((const uint32_t*)&vrB)[jn]);
            float2 xzA = unpack_h2(((const uint32_t*)&vzA)[jn]);
            float2 xzB = unpack_h2(((const uint32_t*)&vzB)[jn]);
            float2 xnA = unpack_h2(((const uint32_t*)&vnA)[jn]);
            float2 xnB = unpack_h2(((const uint32_t*)&vnB)[jn]);
            float2 bh  = *(const float2*)(bhn + q * 32 + jn * 8 + 2 * tig);
            float r0 = sigf(xrA.x), r1 = sigf(xrA.y), r2 = sigf(xrB.x), r3 = sigf(xrB.y);
            float z0 = sigf(xzA.x), z1 = sigf(xzA.y), z2 = sigf(xzB.x), z3 = sigf(xzB.y);
            float n0 = tanhf_(fmaf(r0, bh.x, xnA.x));
            float n1 = tanhf_(fmaf(r1, bh.y, xnA.y));
            float n2 = tanhf_(fmaf(r2, bh.x, xnB.x));
            float n3 = tanhf_(fmaf(r3, bh.y, xnB.y));
            const int kp = 2 * q + (jn >> 1);
            const int off = (jn & 1) * 2;
            aF[kp][off]     = pack_h2(n0 - z0 * n0, n1 - z1 * n1);
            aF[kp][off + 1] = pack_h2(n2 - z2 * n2, n3 - z3 * n3);
        }
    }

    // ---------- t = 1..7 ----------
    #pragma unroll 1
    for (int t = 1; t < KW; ++t) {
        const __half* xt = xqb + (size_t)t * 32;

        #pragma unroll
        for (int q = 0; q < 4; ++q) {
            const __half* pr = xt + (size_t)(0 * 4 + q) * PS_H;
            const __half* pz = xt + (size_t)(1 * 4 + q) * PS_H;
            const __half* pn = xt + (size_t)(2 * 4 + q) * PS_H;

            // ---- phase 1: issue r/z xq loads, then r,z GEMM (hides latency) ----
            uint4 vrA = *(const uint4*)pr, vrB = *(const uint4*)(pr + 256);
            uint4 vzA = *(const uint4*)pz, vzB = *(const uint4*)(pz + 256);

            float ar[4][4], az[4][4];
            #pragma unroll
            for (int jn = 0; jn < 4; ++jn)
                #pragma unroll
                for (int r4 = 0; r4 < 4; ++r4)
                    { ar[jn][r4] = 0.f; az[jn][r4] = 0.f; }
            gemm_q2(ar, az, aF, wA + (uint32_t)(q * 32) * (HS * 2));

            uint32_t rp[8], zp[8];
            #pragma unroll
            for (int jn = 0; jn < 4; ++jn) {
                float2 xrA = unpack_h2(((const uint32_t*)&vrA)[jn]);
                float2 xrB = unpack_h2(((const uint32_t*)&vrB)[jn]);
                float2 xzA = unpack_h2(((const uint32_t*)&vzA)[jn]);
                float2 xzB = unpack_h2(((const uint32_t*)&vzB)[jn]);
                rp[2*jn]   = pack_h2(sigf(ar[jn][0] + xrA.x), sigf(ar[jn][1] + xrA.y));
                rp[2*jn+1] = pack_h2(sigf(ar[jn][2] + xrB.x), sigf(ar[jn][3] + xrB.y));
                zp[2*jn]   = pack_h2(sigf(az[jn][0] + xzA.x), sigf(az[jn][1] + xzA.y));
                zp[2*jn+1] = pack_h2(sigf(az[jn][2] + xzB.x), sigf(az[jn][3] + xzB.y));
            }

            // ---- phase 2: issue n xq loads, then n GEMM ----
            uint4 vnA = *(const uint4*)pn, vnB = *(const uint4*)(pn + 256);

            float an[4][4];
            #pragma unroll
            for (int jn = 0; jn < 4; ++jn)
                #pragma unroll
                for (int r4 = 0; r4 < 4; ++r4)
                    an[jn][r4] = 0.f;
            gemm_q1n(an, aF, wA + (uint32_t)(256 + q * 32) * (HS * 2));

            #pragma unroll
            for (int jn = 0; jn < 4; ++jn) {
                float2 xnA = unpack_h2(((const uint32_t*)&vnA)[jn]);
                float2 xnB = unpack_h2(((const uint32_t*)&vnB)[jn]);
                float2 bh  = *(const float2*)(bhn + q * 32 + jn * 8 + 2 * tig);
                float2 r01 = unpack_h2(rp[2*jn]), r23 = unpack_h2(rp[2*jn+1]);
                float2 z01 = unpack_h2(zp[2*jn]), z23 = unpack_h2(zp[2*jn+1]);

                const int kp = 2 * q + (jn >> 1);
                const int off = (jn & 1) * 2;
                float2 hA = unpack_h2(aF[kp][off]);
                float2 hB = unpack_h2(aF[kp][off + 1]);

                float n0 = tanhf_(fmaf(r01.x, an[jn][0] + bh.x, xnA.x));
                float n1 = tanhf_(fmaf(r01.y, an[jn][1] + bh.y, xnA.y));
                float n2 = tanhf_(fmaf(r23.x, an[jn][2] + bh.x, xnB.x));
                float n3 = tanhf_(fmaf(r23.y, an[jn][3] + bh.y, xnB.y));
                float h0 = n0 + z01.x * (hA.x - n0);
                float h1 = n1 + z01.y * (hA.y - n1);
                float h2 = n2 + z23.x * (hB.x - n2);
                float h3 = n3 + z23.y * (hB.y - n3);
                if (t < KW - 1) {
                    nA[kp][off]     = pack_h2(h0, h1);
                    nA[kp][off + 1] = pack_h2(h2, h3);
                } else {
                    int cc = q * 32 + jn * 8 + 2 * tig;
                    float* oA = out + (size_t)(b * LL + l0 + rA) * DD + cc;
                    float* oB = oA + (size_t)8 * DD;
                    *(float2*)oA = make_float2(h0, h1);
                    *(float2*)oB = make_float2(h2, h3);
                }
            }
        }
        if (t < KW - 1) {
            #pragma unroll
            for (int k = 0; k < 8; ++k)
                #pragma unroll
                for (int r4 = 0; r4 < 4; ++r4)
                    aF[k][r4] = nA[k][r4];
        }
    }
}

// ===================== launch =====================
extern "C" void kernel_launch(void* const* d_in, const int* in_sizes, int n_in,
                              void* d_out, int out_size) {
    const float* x    = (const float*)d_in[0];
    const float* W_ih = (const float*)d_in[1];
    const float* W_hh = (const float*)d_in[2];
    const float* b_ih = (const float*)d_in[3];
    const float* b_hh = (const float*)d_in[4];
    float* out = (float*)d_out;

    cudaFuncSetAttribute(lrnn_pre,  cudaFuncAttributeMaxDynamicSharedMemorySize, PRE_SMEM);
    cudaFuncSetAttribute(lrnn_main, cudaFuncAttributeMaxDynamicSharedMemorySize, MAIN_SMEM);

    lrnn_pre<<<PRE_NC + 1, 512, PRE_SMEM>>>(x, W_ih, b_ih, b_hh);
    lrnn_main<<<MAIN_NC, 512, MAIN_SMEM>>>(W_hh, b_hh, out);
}

// round 14
// speedup vs baseline: 1.0429x; 1.0429x over previous
#include <cuda_runtime.h>
#include <cuda_fp16.h>
#include <cstdint>

// Problem constants
#define KW    8
#define BB    16
#define LL    2048
#define DD    128
#define LP    (LL + 7)      // padded rows per batch
#define GD    384           // 3*D gate dim
#define RT    (BB * LP)     // 32880 total xproj rows
#define NT16  2048          // total 16-row warp-tiles

#define HS    136           // SMEM row stride in halves (272B, conflict-free ldmatrix)
#define W_BYTES (GD * HS * 2)                  // 104448

// both kernels: 512 threads, grid 148 (+1 bias CTA for pre); warp-tile mapping
#define NCTA  148
#define PRE_SMEM (256 * HS * 2 + W_BYTES)      // 174080 (x staging + W)
#define MAIN_SMEM (W_BYTES + 512)              // W + b_hh n-slab cache

// fp16 xproj, plane-major lane-contiguous layout:
//   plane sq = s*4+q (12 planes), then [row RT][tig 4][8 halves]
#define PS_H ((size_t)RT * 32)   // plane stride in halves
__device__ __align__(16) __half g_xq[12 * PS_H];

// ---------------- helpers ----------------
static __device__ __forceinline__ uint32_t smem_u32(const void* p) {
    uint32_t a;
    asm("{ .reg .u64 t; cvta.to.shared.u64 t, %1; cvt.u32.u64 %0, t; }" : "=r"(a) : "l"(p));
    return a;
}
// single-MUFU activations (MUFU.TANH)
static __device__ __forceinline__ float tanhf_(float x) {
    float y; asm("tanh.approx.f32 %0,%1;" : "=f"(y) : "f"(x)); return y;
}
static __device__ __forceinline__ float sigf(float x) {
    return fmaf(0.5f, tanhf_(0.5f * x), 0.5f);
}
static __device__ __forceinline__ void pref_l1(const void* p) {
    asm volatile("prefetch.global.L1 [%0];" :: "l"(p));
}

static __device__ __forceinline__ uint32_t pack_h2(float a, float b) {
    __half2 h = __floats2half2_rn(a, b);
    return *reinterpret_cast<uint32_t*>(&h);
}
static __device__ __forceinline__ float2 unpack_h2(uint32_t u) {
    __half2 h = *reinterpret_cast<__half2*>(&u);
    return make_float2(__low2float(h), __high2float(h));
}

static __device__ __forceinline__ void ldsm4(uint32_t* r, uint32_t addr) {
    asm volatile("ldmatrix.sync.aligned.m8n8.x4.shared.b16 {%0,%1,%2,%3},[%4];"
                 : "=r"(r[0]), "=r"(r[1]), "=r"(r[2]), "=r"(r[3]) : "r"(addr));
}
static __device__ __forceinline__ void mma16816(float* d, const uint32_t* a, const uint32_t* b) {
    asm volatile("mma.sync.aligned.m16n8k16.row.col.f32.f16.f16.f32 "
                 "{%0,%1,%2,%3},{%4,%5,%6,%7},{%8,%9},{%0,%1,%2,%3};"
                 : "+f"(d[0]), "+f"(d[1]), "+f"(d[2]), "+f"(d[3])
                 : "r"(a[0]), "r"(a[1]), "r"(a[2]), "r"(a[3]), "r"(b[0]), "r"(b[1]));
}

// load [384,128] fp32 weight -> fp16 SMEM [384][HS]
template<int NT>
static __device__ __forceinline__ void load_w(__half* wT, const float* __restrict__ W, int tid) {
    #pragma unroll
    for (int j = 0; j < (GD * DD / 4) / NT; ++j) {
        int idx = (tid + j * NT) * 4;
        int g = idx >> 7, k = idx & 127;
        float4 v = *(const float4*)(W + idx);
        __half2* p = (__half2*)&wT[g * HS + k];
        p[0] = __floats2half2_rn(v.x, v.y);
        p[1] = __floats2half2_rn(v.z, v.w);
    }
}

// ===================== Kernel 1: xproj precompute =====================
static __device__ __forceinline__ void gemm_slab16(float acc[16][4], uint32_t aAddr, uint32_t bAddr) {
    #pragma unroll
    for (int k = 0; k < 8; ++k) {
        uint32_t a[4];
        ldsm4(a, aAddr + k * 32);
        #pragma unroll
        for (int np = 0; np < 8; ++np) {
            uint32_t bb[4];
            ldsm4(bb, bAddr + np * (16 * HS * 2) + k * 32);
            mma16816(acc[2 * np],     a, bb);
            mma16816(acc[2 * np + 1], a, bb + 2);
        }
    }
}

__global__ void __launch_bounds__(512, 1)
lrnn_pre(const float* __restrict__ x, const float* __restrict__ W_ih,
         const float* __restrict__ b_ih, const float* __restrict__ b_hh) {
    if (blockIdx.x == NCTA) {   // pad rows: pure bias, plane-major layout
        for (int i = threadIdx.x; i < BB * 7 * GD; i += 512) {
            int b = i / (7 * GD);
            int rr = i % (7 * GD);
            int p = rr / GD, gcol = rr % GD;
            float v = b_ih[gcol] + (gcol < 256 ? b_hh[gcol] : 0.f);
            int s = gcol >> 7, w128 = gcol & 127;
            int q = w128 >> 5, r32 = w128 & 31;
            int jn = r32 >> 3, tg = (r32 & 7) >> 1, ii = r32 & 1;
            size_t rem = (size_t)tg * 8 + jn * 2 + ii;
            g_xq[(size_t)(s * 4 + q) * PS_H + (size_t)(b * LP + p) * 32 + rem] = __float2half_rn(v);
        }
        return;
    }
    extern __shared__ char smem[];
    __half* xT = (__half*)smem;
    __half* wT = (__half*)(smem + 256 * HS * 2);
    int tid = threadIdx.x, w = tid >> 5, lane = tid & 31;

    load_w<512>(wT, W_ih, tid);
    __syncthreads();

    // warp-tile mapping: T = w*148 + cta, active if T < 2048
    int T = w * NCTA + blockIdx.x;
    if (T >= NT16) return;
    int b = T >> 7, gl0 = (T & 127) << 4;

    int m0 = w * 16;                 // local staging region
    int g = lane >> 2, tig = lane & 3;

    {   // stage this warp's 16 x rows (fp32 -> fp16)
        int rloc = lane >> 1;
        int cb = (lane & 1) * 64;
        const float* xr = x + (size_t)(b * LL + gl0 + rloc) * DD + cb;
        __half* dst = &xT[(m0 + rloc) * HS + cb];
        #pragma unroll
        for (int q = 0; q < 16; ++q) {
            float4 v = *(const float4*)(xr + q * 4);
            __half2* p = (__half2*)(dst + q * 4);
            p[0] = __floats2half2_rn(v.x, v.y);
            p[1] = __floats2half2_rn(v.z, v.w);
        }
    }
    __syncwarp();

    uint32_t aAddr = smem_u32(&xT[(m0 + (lane & 15)) * HS + ((lane >> 4) << 3)]);
    int gOff = (lane & 7) + ((lane >> 4) << 3);
    int colOff = ((lane >> 3) & 1) << 3;
    uint32_t wAddr0 = smem_u32(&wT[gOff * HS + colOff]);

    size_t rowA = (size_t)(b * LP + 7 + gl0 + g);

    #pragma unroll 1
    for (int s = 0; s < 3; ++s) {
        float acc[16][4];
        #pragma unroll
        for (int j = 0; j < 16; ++j) { acc[j][0] = acc[j][1] = acc[j][2] = acc[j][3] = 0.f; }
        gemm_slab16(acc, aAddr, wAddr0 + s * (128 * HS * 2));

        int sc = s * 128;
        #pragma unroll
        for (int q = 0; q < 4; ++q) {
            uint32_t pA[4], pB[4];
            #pragma unroll
            for (int jn = 0; jn < 4; ++jn) {
                int j = q * 4 + jn;
                int cc = j * 8 + 2 * tig;
                float2 bi = *(const float2*)(b_ih + sc + cc);
                float bx = 0.f, by = 0.f;
                if (s < 2) { float2 bh = *(const float2*)(b_hh + sc + cc); bx = bh.x; by = bh.y; }
                pA[jn] = pack_h2(acc[j][0] + bi.x + bx, acc[j][1] + bi.y + by);
                pB[jn] = pack_h2(acc[j][2] + bi.x + bx, acc[j][3] + bi.y + by);
            }
            __half* dst = g_xq + (size_t)(s * 4 + q) * PS_H + rowA * 32 + tig * 8;
            *(uint4*)dst = make_uint4(pA[0], pA[1], pA[2], pA[3]);
            *(uint4*)(dst + 8 * 32) = make_uint4(pB[0], pB[1], pB[2], pB[3]);   // row +8
        }
    }
}

// ===================== Kernel 2: 8-step local GRU =====================
// 512 threads, grid 148; warp-tile T = w*148+cta (<=14 active warps/CTA, one
// wave on all 148 SMs). h entirely in registers (aF/nA ping-pong). Fused
// 3-slab GEMM per quarter (R11 form, best measured); 1-MUFU activations.

static __device__ __forceinline__ void gemm_q3(float ar[4][4], float az[4][4], float an[4][4],
                                               const uint32_t aF[8][4], uint32_t bq) {
    #pragma unroll
    for (int k = 0; k < 8; ++k) {
        #pragma unroll
        for (int p = 0; p < 2; ++p) {
            uint32_t br[4], bz[4], bn[4];
            ldsm4(br, bq + p * (16 * HS * 2) + k * 32);
            ldsm4(bz, bq + 128 * HS * 2 + p * (16 * HS * 2) + k * 32);
            ldsm4(bn, bq + 256 * HS * 2 + p * (16 * HS * 2) + k * 32);
            mma16816(ar[2 * p],     aF[k], br);
            mma16816(ar[2 * p + 1], aF[k], br + 2);
            mma16816(az[2 * p],     aF[k], bz);
            mma16816(az[2 * p + 1], aF[k], bz + 2);
            mma16816(an[2 * p],     aF[k], bn);
            mma16816(an[2 * p + 1], aF[k], bn + 2);
        }
    }
}

__global__ void __launch_bounds__(512, 1)
lrnn_main(const float* __restrict__ W_hh, const float* __restrict__ b_hh,
          float* __restrict__ out) {
    extern __shared__ char smem[];
    __half* wT = (__half*)smem;
    float* bhn = (float*)(smem + W_BYTES);
    int tid = threadIdx.x, w = tid >> 5, lane = tid & 31;

    load_w<512>(wT, W_hh, tid);
    if (tid < 128) bhn[tid] = b_hh[256 + tid];
    __syncthreads();

    int T = w * NCTA + blockIdx.x;
    if (T >= NT16) return;
    int b = T >> 7, gl0 = (T & 127) << 4;

    int g = lane >> 2, tig = lane & 3;

    int gOff = (lane & 7) + ((lane >> 4) << 3);
    int colOff = ((lane >> 3) & 1) << 3;
    uint32_t wA = smem_u32(&wT[gOff * HS + colOff]);

    // per-thread xq base (plane-relative): row at window step t -> +t*32 halves
    const __half* xqb = g_xq + (size_t)(b * LP + gl0 + g) * 32 + tig * 8;

    uint32_t aF[8][4], nA[8][4];

    // ---------- t = 0 (h_prev = 0) ----------
    #pragma unroll
    for (int q = 0; q < 4; ++q) {
        const __half* pr = xqb + (size_t)(0 * 4 + q) * PS_H;
        const __half* pz = xqb + (size_t)(1 * 4 + q) * PS_H;
        const __half* pn = xqb + (size_t)(2 * 4 + q) * PS_H;
        uint4 vrA = *(const uint4*)pr,         vrB = *(const uint4*)(pr + 256);
        uint4 vzA = *(const uint4*)pz,         vzB = *(const uint4*)(pz + 256);
        uint4 vnA = *(const uint4*)pn,         vnB = *(const uint4*)(pn + 256);
        #pragma unroll
        for (int jn = 0; jn < 4; ++jn) {
            float2 xrA = unpack_h2(((const uint32_t*)&vrA)[jn]);
            float2 xrB = unpack_h2(((const uint32_t*)&vrB)[jn]);
            float2 xzA = unpack_h2(((const uint32_t*)&vzA)[jn]);
            float2 xzB = unpack_h2(((const uint32_t*)&vzB)[jn]);
            float2 xnA = unpack_h2(((const uint32_t*)&vnA)[jn]);
            float2 xnB = unpack_h2(((const uint32_t*)&vnB)[jn]);
            float2 bh  = *(const float2*)(bhn + q * 32 + jn * 8 + 2 * tig);
            float r0 = sigf(xrA.x), r1 = sigf(xrA.y), r2 = sigf(xrB.x), r3 = sigf(xrB.y);
            float z0 = sigf(xzA.x), z1 = sigf(xzA.y), z2 = sigf(xzB.x), z3 = sigf(xzB.y);
            float n0 = tanhf_(fmaf(r0, bh.x, xnA.x));
            float n1 = tanhf_(fmaf(r1, bh.y, xnA.y));
            float n2 = tanhf_(fmaf(r2, bh.x, xnB.x));
            float n3 = tanhf_(fmaf(r3, bh.y, xnB.y));
            const int kp = 2 * q + (jn >> 1);
            const int off = (jn & 1) * 2;
            aF[kp][off]     = pack_h2(n0 - z0 * n0, n1 - z1 * n1);
            aF[kp][off + 1] = pack_h2(n2 - z2 * n2, n3 - z3 * n3);
        }
    }

    // ---------- t = 1..7 ----------
    #pragma unroll 1
    for (int t = 1; t < KW; ++t) {
        const __half* xt = xqb + (size_t)t * 32;

        #pragma unroll
        for (int q = 0; q < 4; ++q) {
            const __half* pr = xt + (size_t)(0 * 4 + q) * PS_H;
            const __half* pz = xt + (size_t)(1 * 4 + q) * PS_H;
            const __half* pn = xt + (size_t)(2 * 4 + q) * PS_H;
            pref_l1(pr); pref_l1(pr + 256);
            pref_l1(pz); pref_l1(pz + 256);
            pref_l1(pn); pref_l1(pn + 256);

            float ar[4][4], az[4][4], an[4][4];
            #pragma unroll
            for (int jn = 0; jn < 4; ++jn)
                #pragma unroll
                for (int r4 = 0; r4 < 4; ++r4)
                    { ar[jn][r4] = 0.f; az[jn][r4] = 0.f; an[jn][r4] = 0.f; }

            gemm_q3(ar, az, an, aF, wA + (uint32_t)(q * 32) * (HS * 2));

            uint4 vrA = *(const uint4*)pr, vrB = *(const uint4*)(pr + 256);
            uint4 vzA = *(const uint4*)pz, vzB = *(const uint4*)(pz + 256);
            uint4 vnA = *(const uint4*)pn, vnB = *(const uint4*)(pn + 256);
            #pragma unroll
            for (int jn = 0; jn < 4; ++jn) {
                float2 xrA = unpack_h2(((const uint32_t*)&vrA)[jn]);
                float2 xrB = unpack_h2(((const uint32_t*)&vrB)[jn]);
                float2 xzA = unpack_h2(((const uint32_t*)&vzA)[jn]);
                float2 xzB = unpack_h2(((const uint32_t*)&vzB)[jn]);
                float2 xnA = unpack_h2(((const uint32_t*)&vnA)[jn]);
                float2 xnB = unpack_h2(((const uint32_t*)&vnB)[jn]);
                float2 bh  = *(const float2*)(bhn + q * 32 + jn * 8 + 2 * tig);

                float r0 = sigf(ar[jn][0] + xrA.x);
                float r1 = sigf(ar[jn][1] + xrA.y);
                float r2 = sigf(ar[jn][2] + xrB.x);
                float r3 = sigf(ar[jn][3] + xrB.y);
                float z0 = sigf(az[jn][0] + xzA.x);
                float z1 = sigf(az[jn][1] + xzA.y);
                float z2 = sigf(az[jn][2] + xzB.x);
                float z3 = sigf(az[jn][3] + xzB.y);

                const int kp = 2 * q + (jn >> 1);
                const int off = (jn & 1) * 2;
                float2 hA = unpack_h2(aF[kp][off]);
                float2 hB = unpack_h2(aF[kp][off + 1]);

                float n0 = tanhf_(fmaf(r0, an[jn][0] + bh.x, xnA.x));
                float n1 = tanhf_(fmaf(r1, an[jn][1] + bh.y, xnA.y));
                float n2 = tanhf_(fmaf(r2, an[jn][2] + bh.x, xnB.x));
                float n3 = tanhf_(fmaf(r3, an[jn][3] + bh.y, xnB.y));
                float h0 = n0 + z0 * (hA.x - n0);
                float h1 = n1 + z1 * (hA.y - n1);
                float h2 = n2 + z2 * (hB.x - n2);
                float h3 = n3 + z3 * (hB.y - n3);
                if (t < KW - 1) {
                    nA[kp][off]     = pack_h2(h0, h1);
                    nA[kp][off + 1] = pack_h2(h2, h3);
                } else {
                    int cc = q * 32 + jn * 8 + 2 * tig;
                    float* oA = out + (size_t)(b * LL + gl0 + g) * DD + cc;
                    float* oB = oA + (size_t)8 * DD;
                    *(float2*)oA = make_float2(h0, h1);
                    *(float2*)oB = make_float2(h2, h3);
                }
            }
        }
        if (t < KW - 1) {
            #pragma unroll
            for (int k = 0; k < 8; ++k)
                #pragma unroll
                for (int r4 = 0; r4 < 4; ++r4)
                    aF[k][r4] = nA[k][r4];
        }
    }
}

// ===================== launch =====================
extern "C" void kernel_launch(void* const* d_in, const int* in_sizes, int n_in,
                              void* d_out, int out_size) {
    const float* x    = (const float*)d_in[0];
    const float* W_ih = (const float*)d_in[1];
    const float* W_hh = (const float*)d_in[2];
    const float* b_ih = (const float*)d_in[3];
    const float* b_hh = (const float*)d_in[4];
    float* out = (float*)d_out;

    cudaFuncSetAttribute(lrnn_pre,  cudaFuncAttributeMaxDynamicSharedMemorySize, PRE_SMEM);
    cudaFuncSetAttribute(lrnn_main, cudaFuncAttributeMaxDynamicSharedMemorySize, MAIN_SMEM);

    lrnn_pre<<<NCTA + 1, 512, PRE_SMEM>>>(x, W_ih, b_ih, b_hh);
    lrnn_main<<<NCTA, 512, MAIN_SMEM>>>(W_hh, b_hh, out);
}